// round 1
// baseline (speedup 1.0000x reference)
#include <cuda_runtime.h>

// EMA with alpha=0.2. Output per row i is e_{idx} with idx = max(len[i],1)-1.
// e_n = 0.8^n x_0 + 0.2 * sum_{j=1..n} 0.8^{n-j} x_j.
// Weights decay geometrically: 0.8^127 ~ 5e-13, so only the trailing
// TAPS=128 samples of each row matter to fp32 precision. For rows with
// idx < TAPS the result is exact (window starts at x_0).
//
// One warp per row: coalesced loads of the <=128-float window, per-lane
// weight via exp2f, FMA accumulate, warp shuffle reduction.

#define TAPS 128
#define LOG2_08 (-0.32192809488736234787f) // log2(0.8)

__global__ void __launch_bounds__(256)
ema_last_kernel(const float* __restrict__ x,
                const int* __restrict__ valid_len,
                float* __restrict__ out,
                int B, int T)
{
    int warp = (int)((blockIdx.x * blockDim.x + threadIdx.x) >> 5);
    int lane = threadIdx.x & 31;
    if (warp >= B) return;

    int len = valid_len[warp];
    int n = (len > 1 ? len : 1) - 1;          // target index idx = L-1
    int m = n < (TAPS - 1) ? n : (TAPS - 1);  // window length - 1
    const float* xr = x + (size_t)warp * (size_t)T + (size_t)(n - m);

    float acc = 0.0f;
#pragma unroll
    for (int k = 0; k < TAPS / 32; ++k) {
        int t = lane + 32 * k;
        if (t <= m) {
            // weight of window element t:
            //   t == 0 : 0.8^m   (exact seed coefficient when window starts at x_0;
            //                     ~1e-12 absolute approximation otherwise)
            //   t >= 1 : 0.2 * 0.8^(m - t)
            float w = (t == 0) ? exp2f((float)m * LOG2_08)
                               : 0.2f * exp2f((float)(m - t) * LOG2_08);
            acc = fmaf(w, xr[t], acc);
        }
    }

    // warp reduction
#pragma unroll
    for (int off = 16; off > 0; off >>= 1)
        acc += __shfl_xor_sync(0xffffffffu, acc, off);

    if (lane == 0) out[warp] = acc;
}

extern "C" void kernel_launch(void* const* d_in, const int* in_sizes, int n_in,
                              void* d_out, int out_size)
{
    const float* pop_history = (const float*)d_in[0];
    const int*   valid_len   = (const int*)d_in[1];
    float*       out         = (float*)d_out;

    int B = in_sizes[1];               // 16384
    int T = in_sizes[0] / in_sizes[1]; // 2048

    int threads = 256;                       // 8 warps/block -> 8 rows/block
    int blocks = (B * 32 + threads - 1) / threads;
    ema_last_kernel<<<blocks, threads>>>(pop_history, valid_len, out, B, T);
}

// round 2
// speedup vs baseline: 1.3462x; 1.3462x over previous
#include <cuda_runtime.h>

// EMA with alpha=0.2. Output per row i is e_{idx}, idx = max(len[i],1)-1.
// e_n = 0.8^n x_0 + 0.2 * sum_{j=1..n} 0.8^{n-j} x_j.
// Tap weight decays as 0.2*0.8^t from the end; 0.8^63 ~ 7.8e-7, so a
// 64-tap trailing window reproduces the EMA to ~1e-6 relative (threshold
// is 1e-3). Rows with idx < 64 are computed exactly from x_0.
//
// One warp per row: 2 unconditional coalesced loads per lane (out-of-window
// taps stay inside the row and get weight 0), exp2f weights, FMA, shfl-reduce.

#define TAPS 64
#define LOG2_08 (-0.32192809488736234787f) // log2(0.8)

__global__ void __launch_bounds__(256)
ema_last_kernel(const float* __restrict__ x,
                const int* __restrict__ valid_len,
                float* __restrict__ out,
                int B, int T)
{
    int warp = (int)((blockIdx.x * blockDim.x + threadIdx.x) >> 5);
    int lane = threadIdx.x & 31;
    if (warp >= B) return;

    int len = valid_len[warp];
    int n = (len > 1 ? len : 1) - 1;          // target index idx = L-1
    int m = n < (TAPS - 1) ? n : (TAPS - 1);  // window length - 1
    const float* xr = x + (size_t)warp * (size_t)T + (size_t)(n - m);

    // Both taps loaded unconditionally: window start is n-m >= 0 and
    // indices t in [0,63] stay within the 2048-float row. Invalid taps
    // (t > m, only when n < 63) get weight 0.
    int   t0 = lane,          t1 = lane + 32;
    float x0 = xr[t0];
    float x1 = xr[t1];

    // weight(t) = 0.8^m          for t == 0 (seed coefficient)
    //           = 0.2*0.8^(m-t)  for 1 <= t <= m
    float w0 = 0.2f * exp2f((float)(m - t0) * LOG2_08);
    float w1 = 0.2f * exp2f((float)(m - t1) * LOG2_08);
    if (t0 == 0) w0 *= 5.0f;        // lane 0: seed tap
    if (t0 > m)  w0 = 0.0f;
    if (t1 > m)  w1 = 0.0f;

    float acc = fmaf(w0, x0, w1 * x1);

#pragma unroll
    for (int off = 16; off > 0; off >>= 1)
        acc += __shfl_xor_sync(0xffffffffu, acc, off);

    if (lane == 0) out[warp] = acc;
}

extern "C" void kernel_launch(void* const* d_in, const int* in_sizes, int n_in,
                              void* d_out, int out_size)
{
    const float* pop_history = (const float*)d_in[0];
    const int*   valid_len   = (const int*)d_in[1];
    float*       out         = (float*)d_out;

    int B = in_sizes[1];               // 16384
    int T = in_sizes[0] / in_sizes[1]; // 2048

    int threads = 256;                 // 8 warps/block -> 8 rows/block
    int blocks = (B * 32 + threads - 1) / threads;
    ema_last_kernel<<<blocks, threads>>>(pop_history, valid_len, out, B, T);
}